// round 7
// baseline (speedup 1.0000x reference)
#include <cuda_runtime.h>
#include <cuda_fp16.h>
#include <cuda_bf16.h>
#include <cstdint>

// Problem constants (fixed by reference)
#define BB 32
#define TT 256
#define CC 512
#define LL 25

// Scratch in device globals (no allocations allowed in kernel_launch)
__device__ float g_wf[BB * TT * CC];        // 16 MB: post-FC features
__device__ float g_scores[BB * LL * TT];    // 0.8 MB: attention logits

// ---------------------------------------------------------------------------
__device__ __forceinline__ __half2 htanh2(__half2 x) {
    uint32_t xu = *(uint32_t*)&x, yu;
    asm("tanh.approx.f16x2 %0, %1;" : "=r"(yu) : "r"(xu));
    return *(__half2*)&yu;
}
__device__ __forceinline__ __half2 packh2(float lo, float hi) {
    return __float22half2_rn(make_float2(lo, hi));
}

// ---------------------------------------------------------------------------
// Kernel A: wf[m,n] = sum_k X[m,k] * W[n,k] + bias[n]
// fp16 mma m16n8k16, fp32 accum. Block 128(m)x64(n), BK=16, 128 threads
// (4 warps, warp tile 64x32), double-buffered SMEM, grid=512 CTAs
// -> ~3.5 CTAs/SM in ONE wave (vs 1.73 before).
// ---------------------------------------------------------------------------
#define PADH 24
__global__ __launch_bounds__(128, 4) void wf_gemm_fp16(
    const float* __restrict__ X,     // [8192, 512]
    const float* __restrict__ W,     // [512, 512] (row n, col k)
    const float* __restrict__ bias)  // [512]
{
    __shared__ __half As[2][128][PADH];  // 12.3 KB
    __shared__ __half Bs[2][64][PADH];   //  6.2 KB

    const int tid  = threadIdx.x;
    const int lane = tid & 31;
    const int warp = tid >> 5;           // 0..3
    const int g    = lane >> 2;          // 0..7
    const int tg   = lane & 3;           // 0..3
    const int wm   = (warp >> 1) << 6;   // 0, 64
    const int wn   = (warp & 1) << 5;    // 0, 32

    const int m0 = blockIdx.y << 7;      // M tile (128)
    const int n0 = blockIdx.x << 6;      // N tile (64)

    // A: one row per thread (tid = 0..127), 16 floats along k
    const float* Ag = X + (m0 + tid) * CC;
    // B: row tid>>1 (0..63), k-offset (tid&1)*8
    const int brow = tid >> 1;
    const int bcol = (tid & 1) << 3;
    const float* Bg = W + (n0 + brow) * CC + bcol;

    float acc[4][4][4];
#pragma unroll
    for (int mt = 0; mt < 4; mt++)
#pragma unroll
        for (int nt = 0; nt < 4; nt++)
#pragma unroll
            for (int i = 0; i < 4; i++) acc[mt][nt][i] = 0.f;

    float4 a4[4], b4[2];

#define CVT_STORE(dst, v)                                                     \
    do {                                                                      \
        __half2 h0 = __float22half2_rn(make_float2((v).x, (v).y));            \
        __half2 h1 = __float22half2_rn(make_float2((v).z, (v).w));            \
        *(uint2*)(dst) = make_uint2(*(uint32_t*)&h0, *(uint32_t*)&h1);        \
    } while (0)

#define GEMM_STORE_TILE(SS)                                                   \
    do {                                                                      \
        CVT_STORE(&As[SS][tid][0],  a4[0]);                                   \
        CVT_STORE(&As[SS][tid][4],  a4[1]);                                   \
        CVT_STORE(&As[SS][tid][8],  a4[2]);                                   \
        CVT_STORE(&As[SS][tid][12], a4[3]);                                   \
        CVT_STORE(&Bs[SS][brow][bcol],     b4[0]);                            \
        CVT_STORE(&Bs[SS][brow][bcol + 4], b4[1]);                            \
    } while (0)

    // prologue: tile 0
#pragma unroll
    for (int j = 0; j < 4; j++) a4[j] = *(const float4*)(Ag + 4 * j);
    b4[0] = *(const float4*)(Bg);
    b4[1] = *(const float4*)(Bg + 4);
    GEMM_STORE_TILE(0);
    __syncthreads();

    int s = 0;
    for (int it = 0; it < 32; ++it) {
        if (it < 31) {
            const int ko = (it + 1) << 4;
#pragma unroll
            for (int j = 0; j < 4; j++) a4[j] = *(const float4*)(Ag + ko + 4 * j);
            b4[0] = *(const float4*)(Bg + ko);
            b4[1] = *(const float4*)(Bg + ko + 4);
        }
        {
            uint32_t af[4][4], bf[4][2];
#pragma unroll
            for (int mt = 0; mt < 4; mt++) {
                const int r = wm + (mt << 4) + g;
                af[mt][0] = *(const uint32_t*)&As[s][r][2 * tg];
                af[mt][1] = *(const uint32_t*)&As[s][r + 8][2 * tg];
                af[mt][2] = *(const uint32_t*)&As[s][r][2 * tg + 8];
                af[mt][3] = *(const uint32_t*)&As[s][r + 8][2 * tg + 8];
            }
#pragma unroll
            for (int nt = 0; nt < 4; nt++) {
                const int r = wn + (nt << 3) + g;
                bf[nt][0] = *(const uint32_t*)&Bs[s][r][2 * tg];
                bf[nt][1] = *(const uint32_t*)&Bs[s][r][2 * tg + 8];
            }
#pragma unroll
            for (int mt = 0; mt < 4; mt++)
#pragma unroll
                for (int nt = 0; nt < 4; nt++) {
                    asm volatile(
                        "mma.sync.aligned.m16n8k16.row.col.f32.f16.f16.f32 "
                        "{%0,%1,%2,%3}, {%4,%5,%6,%7}, {%8,%9}, {%0,%1,%2,%3};"
                        : "+f"(acc[mt][nt][0]), "+f"(acc[mt][nt][1]),
                          "+f"(acc[mt][nt][2]), "+f"(acc[mt][nt][3])
                        : "r"(af[mt][0]), "r"(af[mt][1]),
                          "r"(af[mt][2]), "r"(af[mt][3]),
                          "r"(bf[nt][0]), "r"(bf[nt][1]));
                }
        }
        if (it < 31) {
            const int ns = s ^ 1;
            GEMM_STORE_TILE(ns);
            __syncthreads();
            s = ns;
        }
    }

    // Epilogue: add bias, store.
    // C frag: c0:(g,2tg) c1:(g,2tg+1) c2:(g+8,2tg) c3:(g+8,2tg+1)
#pragma unroll
    for (int nt = 0; nt < 4; nt++) {
        const int n = n0 + wn + (nt << 3) + (tg << 1);
        const float b0v = bias[n];
        const float b1v = bias[n + 1];
#pragma unroll
        for (int mt = 0; mt < 4; mt++) {
            const int m = m0 + wm + (mt << 4) + g;
            float2 v0 = make_float2(acc[mt][nt][0] + b0v, acc[mt][nt][1] + b1v);
            float2 v1 = make_float2(acc[mt][nt][2] + b0v, acc[mt][nt][3] + b1v);
            *(float2*)&g_wf[m * CC + n]       = v0;
            *(float2*)&g_wf[(m + 8) * CC + n] = v1;
        }
    }
#undef GEMM_STORE_TILE
#undef CVT_STORE
}

// ---------------------------------------------------------------------------
// Kernel B1 v4: scores[b,l,t] = sum_c tanh(wf[b,t,c]+pos[l,c])*aw[c] + ab
// tanh via f16x2 MUFU (2 elem/op — TANH is quarter-rate, this halves the
// binding pipe). Args in half2 (HADD2), accumulation in fp32.
// One warp per FOUR t-rows. grid = (T/32, B), 256 threads.
// ---------------------------------------------------------------------------
__global__ __launch_bounds__(256) void scores_kernel(
    const float* __restrict__ pos_emb,   // [25, 512]
    const float* __restrict__ atten_w,   // [512]
    const float* __restrict__ atten_b)   // [1]
{
    const int warp = threadIdx.x >> 5;
    const int lane = threadIdx.x & 31;
    const int b = blockIdx.y;
    const int t0 = blockIdx.x * 32 + warp * 4;

    const float4* awr = (const float4*)atten_w;

    // wf pre-packed to half2: 4 rows x 8 half2 (16 c) per lane
    __half2 wfh[4][8];
    float4 aw4[4];
#pragma unroll
    for (int r = 0; r < 4; r++) {
        const float4* wfr = (const float4*)(g_wf + (b * TT + t0 + r) * CC);
#pragma unroll
        for (int i = 0; i < 4; i++) {
            float4 v = wfr[lane + 32 * i];
            wfh[r][2 * i]     = packh2(v.x, v.y);
            wfh[r][2 * i + 1] = packh2(v.z, v.w);
        }
    }
#pragma unroll
    for (int i = 0; i < 4; i++) aw4[i] = awr[lane + 32 * i];
    const float bsc = atten_b[0];

#pragma unroll 2
    for (int l = 0; l < LL; l++) {
        const float4* pr = (const float4*)(pos_emb + l * CC);
        float acc0 = 0.f, acc1 = 0.f, acc2 = 0.f, acc3 = 0.f;
#pragma unroll
        for (int i = 0; i < 4; i++) {
            float4 p = __ldg(&pr[lane + 32 * i]);
            __half2 p01 = packh2(p.x, p.y);
            __half2 p23 = packh2(p.z, p.w);

            __half2 tA0 = htanh2(__hadd2(wfh[0][2 * i], p01));
            __half2 tA1 = htanh2(__hadd2(wfh[0][2 * i + 1], p23));
            __half2 tB0 = htanh2(__hadd2(wfh[1][2 * i], p01));
            __half2 tB1 = htanh2(__hadd2(wfh[1][2 * i + 1], p23));
            __half2 tC0 = htanh2(__hadd2(wfh[2][2 * i], p01));
            __half2 tC1 = htanh2(__hadd2(wfh[2][2 * i + 1], p23));
            __half2 tD0 = htanh2(__hadd2(wfh[3][2 * i], p01));
            __half2 tD1 = htanh2(__hadd2(wfh[3][2 * i + 1], p23));

            acc0 = fmaf(__low2float(tA0),  aw4[i].x, acc0);
            acc0 = fmaf(__high2float(tA0), aw4[i].y, acc0);
            acc0 = fmaf(__low2float(tA1),  aw4[i].z, acc0);
            acc0 = fmaf(__high2float(tA1), aw4[i].w, acc0);
            acc1 = fmaf(__low2float(tB0),  aw4[i].x, acc1);
            acc1 = fmaf(__high2float(tB0), aw4[i].y, acc1);
            acc1 = fmaf(__low2float(tB1),  aw4[i].z, acc1);
            acc1 = fmaf(__high2float(tB1), aw4[i].w, acc1);
            acc2 = fmaf(__low2float(tC0),  aw4[i].x, acc2);
            acc2 = fmaf(__high2float(tC0), aw4[i].y, acc2);
            acc2 = fmaf(__low2float(tC1),  aw4[i].z, acc2);
            acc2 = fmaf(__high2float(tC1), aw4[i].w, acc2);
            acc3 = fmaf(__low2float(tD0),  aw4[i].x, acc3);
            acc3 = fmaf(__high2float(tD0), aw4[i].y, acc3);
            acc3 = fmaf(__low2float(tD1),  aw4[i].z, acc3);
            acc3 = fmaf(__high2float(tD1), aw4[i].w, acc3);
        }
#pragma unroll
        for (int s = 16; s; s >>= 1) {
            acc0 += __shfl_xor_sync(0xffffffffu, acc0, s);
            acc1 += __shfl_xor_sync(0xffffffffu, acc1, s);
            acc2 += __shfl_xor_sync(0xffffffffu, acc2, s);
            acc3 += __shfl_xor_sync(0xffffffffu, acc3, s);
        }
        if (lane == 0) {
            *(float4*)&g_scores[(b * LL + l) * TT + t0] =
                make_float4(acc0 + bsc, acc1 + bsc, acc2 + bsc, acc3 + bsc);
        }
    }
}

// ---------------------------------------------------------------------------
// Kernel B2: softmax over t, then pvam[b,l,c] = sum_t attn[l,t]*wf[b,t,c]
// grid = (C/256, B), 256 threads. attn via float4 (4 t per LDS.128).
// ---------------------------------------------------------------------------
__global__ __launch_bounds__(256) void pvam_kernel(float* __restrict__ out)
{
    __shared__ float attn_s[LL * TT];  // 25.6 KB
    const int b = blockIdx.y;
    const int tid = threadIdx.x;
    const int warp = tid >> 5;
    const int lane = tid & 31;

    for (int l = warp; l < LL; l += 8) {
        const float* sr = g_scores + (b * LL + l) * TT;
        float v[8];
        float m = -1e30f;
#pragma unroll
        for (int i = 0; i < 8; i++) {
            v[i] = sr[lane + 32 * i];
            m = fmaxf(m, v[i]);
        }
#pragma unroll
        for (int s = 16; s; s >>= 1) m = fmaxf(m, __shfl_xor_sync(0xffffffffu, m, s));
        float ssum = 0.f;
#pragma unroll
        for (int i = 0; i < 8; i++) {
            float e = __expf(v[i] - m);
            attn_s[l * TT + lane + 32 * i] = e;
            ssum += e;
        }
#pragma unroll
        for (int s = 16; s; s >>= 1) ssum += __shfl_xor_sync(0xffffffffu, ssum, s);
        float inv = __fdividef(1.f, ssum);
#pragma unroll
        for (int i = 0; i < 8; i++) attn_s[l * TT + lane + 32 * i] *= inv;
    }
    __syncthreads();

    const int c = blockIdx.x * 256 + tid;
    const float* wfb = g_wf + (b * TT) * CC + c;
    float acc[LL];
#pragma unroll
    for (int l = 0; l < LL; l++) acc[l] = 0.f;

    for (int t4 = 0; t4 < TT; t4 += 4) {
        float w0 = wfb[(t4 + 0) * CC];
        float w1 = wfb[(t4 + 1) * CC];
        float w2 = wfb[(t4 + 2) * CC];
        float w3 = wfb[(t4 + 3) * CC];
#pragma unroll
        for (int l = 0; l < LL; l++) {
            float4 a = *(const float4*)&attn_s[l * TT + t4];
            float s0 = fmaf(a.x, w0, acc[l]);
            float s1 = fmaf(a.y, w1, s0);
            float s2 = fmaf(a.z, w2, s1);
            acc[l] = fmaf(a.w, w3, s2);
        }
    }

    float* o = out + (b * LL) * CC + c;
#pragma unroll
    for (int l = 0; l < LL; l++) o[l * CC] = acc[l];
}

// ---------------------------------------------------------------------------
extern "C" void kernel_launch(void* const* d_in, const int* in_sizes, int n_in,
                              void* d_out, int out_size)
{
    const float* word_features = (const float*)d_in[0];  // (32,256,512)
    const float* word_fc_w     = (const float*)d_in[1];  // (512,512)
    const float* word_fc_b     = (const float*)d_in[2];  // (512,)
    const float* pos_emb       = (const float*)d_in[3];  // (25,512)
    const float* atten_w       = (const float*)d_in[4];  // (512,)
    const float* atten_b       = (const float*)d_in[5];  // (1,)
    float* out = (float*)d_out;                          // (32,25,512)

    wf_gemm_fp16<<<dim3(CC / 64, (BB * TT) / 128), 128>>>(
        word_features, word_fc_w, word_fc_b);
    scores_kernel<<<dim3(TT / 32, BB), 256>>>(pos_emb, atten_w, atten_b);
    pvam_kernel<<<dim3(CC / 256, BB), 256>>>(out);
}

// round 10
// speedup vs baseline: 1.1478x; 1.1478x over previous
#include <cuda_runtime.h>
#include <cuda_fp16.h>
#include <cuda_bf16.h>
#include <cstdint>

// Problem constants (fixed by reference)
#define BB 32
#define TT 256
#define CC 512
#define LL 25

// Scratch in device globals (no allocations allowed in kernel_launch)
__device__ float  g_wf[BB * TT * CC];        // 16 MB: post-FC features
__device__ float  g_scores[BB * LL * TT];    // 0.8 MB: attention logits
__device__ __half g_xh[BB * TT * CC];        // 8 MB: X in fp16
__device__ __half g_wh[CC * CC];             // 0.5 MB: W in fp16

// ---------------------------------------------------------------------------
__device__ __forceinline__ float htanh(float x) {
    float y;
    asm("tanh.approx.f32 %0, %1;" : "=f"(y) : "f"(x));
    return y;
}
// Rational tanh on the FMA pipe (Eigen-style): ~12 FFMA + 1 MUFU.RCP, |err|~1e-6
__device__ __forceinline__ float tanh_poly(float x) {
    x = fminf(fmaxf(x, -7.90531110763549805f), 7.90531110763549805f);
    float x2 = x * x;
    float p = fmaf(x2, -2.76076847742355e-16f, 2.00018790482477e-13f);
    p = fmaf(p, x2, -8.60467152213735e-11f);
    p = fmaf(p, x2, 5.12229709037114e-08f);
    p = fmaf(p, x2, 1.48572235717979e-05f);
    p = fmaf(p, x2, 6.37261928875436e-04f);
    p = fmaf(p, x2, 4.89352455891786e-03f);
    p = x * p;
    float q = fmaf(x2, 1.19825839466702e-06f, 1.18534705686654e-04f);
    q = fmaf(q, x2, 2.26843463243900e-03f);
    q = fmaf(q, x2, 4.89352518554385e-03f);
    return __fdividef(p, q);
}

__device__ __forceinline__ void cp16(uint32_t smem_dst, const void* gmem_src) {
    asm volatile("cp.async.cg.shared.global [%0], [%1], 16;"
                 :: "r"(smem_dst), "l"(gmem_src));
}
#define CP_COMMIT asm volatile("cp.async.commit_group;")
#define CP_WAIT2  asm volatile("cp.async.wait_group 2;")

// ---------------------------------------------------------------------------
// Kernel 0: convert X [8192x512] and W [512x512] fp32 -> fp16 once.
// ---------------------------------------------------------------------------
__global__ __launch_bounds__(256) void cvt_to_half(
    const float* __restrict__ X, const float* __restrict__ W)
{
    const int NX = BB * TT * CC / 4;
    const int NW = CC * CC / 4;
    int i = blockIdx.x * 256 + threadIdx.x;
    if (i < NX) {
        float4 v = ((const float4*)X)[i];
        __half2 h0 = __float22half2_rn(make_float2(v.x, v.y));
        __half2 h1 = __float22half2_rn(make_float2(v.z, v.w));
        *(uint2*)&g_xh[4 * i] = make_uint2(*(uint32_t*)&h0, *(uint32_t*)&h1);
    } else if (i < NX + NW) {
        int j = i - NX;
        float4 v = ((const float4*)W)[j];
        __half2 h0 = __float22half2_rn(make_float2(v.x, v.y));
        __half2 h1 = __float22half2_rn(make_float2(v.z, v.w));
        *(uint2*)&g_wh[4 * j] = make_uint2(*(uint32_t*)&h0, *(uint32_t*)&h1);
    }
}

// ---------------------------------------------------------------------------
// Kernel A: wf[m,n] = sum_k X[m,k] * W[n,k] + bias[n]
// fp16 mma m16n8k16, fp32 accum. Block 128x128, BK=32, 256 threads,
// cp.async 4-stage pipeline (fp16 sources). 16 main-loop iterations.
// SMEM rows padded to PADK=40 halves (20 words): fragment LDS bank
// (20g+tg)%32 distinct across the warp -> conflict-free.
// ---------------------------------------------------------------------------
#define PADK 40
#define NSTG 4
#define A_HALVES (NSTG * 128 * PADK)   // 20480 halves
__global__ __launch_bounds__(256, 2) void wf_gemm_pipe(
    const float* __restrict__ bias)    // [512]
{
    extern __shared__ __half sm[];
    __half (*As)[128][PADK] = (__half(*)[128][PADK])sm;
    __half (*Bs)[128][PADK] = (__half(*)[128][PADK])(sm + A_HALVES);
    const uint32_t sa = (uint32_t)__cvta_generic_to_shared(sm);
    const uint32_t sb = sa + A_HALVES * 2;

    const int tid  = threadIdx.x;
    const int lane = tid & 31;
    const int warp = tid >> 5;
    const int g    = lane >> 2;          // 0..7
    const int tg   = lane & 3;           // 0..3
    const int wm   = (warp >> 2) << 6;   // 0, 64
    const int wn   = (warp & 3) << 5;    // 0, 32, 64, 96

    const int m0 = blockIdx.y << 7;
    const int n0 = blockIdx.x << 7;

    // copy slots: chunks tid and tid+256; row = c>>2, koff = (c&3)*8 halves
    const int r0 = tid >> 2;
    const int r1 = (tid + 256) >> 2;
    const int ko = (tid & 3) << 3;
    const __half* Axg = g_xh + (m0 + r0) * CC + ko;
    const __half* Axg1 = g_xh + (m0 + r1) * CC + ko;
    const __half* Bwg = g_wh + (n0 + r0) * CC + ko;
    const __half* Bwg1 = g_wh + (n0 + r1) * CC + ko;
    const uint32_t dA0 = sa + (r0 * PADK + ko) * 2;
    const uint32_t dA1 = sa + (r1 * PADK + ko) * 2;
    const uint32_t dB0 = sb + (r0 * PADK + ko) * 2;
    const uint32_t dB1 = sb + (r1 * PADK + ko) * 2;
    const uint32_t stgb = 128 * PADK * 2;  // bytes per stage

#define ISSUE(S, K0)                                  \
    do {                                              \
        cp16(dA0 + (S) * stgb, Axg  + (K0));          \
        cp16(dA1 + (S) * stgb, Axg1 + (K0));          \
        cp16(dB0 + (S) * stgb, Bwg  + (K0));          \
        cp16(dB1 + (S) * stgb, Bwg1 + (K0));          \
    } while (0)

    float acc[4][4][4];
#pragma unroll
    for (int mt = 0; mt < 4; mt++)
#pragma unroll
        for (int nt = 0; nt < 4; nt++)
#pragma unroll
            for (int i = 0; i < 4; i++) acc[mt][nt][i] = 0.f;

    // prologue: stages 0..2
    ISSUE(0, 0);   CP_COMMIT;
    ISSUE(1, 32);  CP_COMMIT;
    ISSUE(2, 64);  CP_COMMIT;

    for (int it = 0; it < 16; ++it) {
        CP_WAIT2;
        __syncthreads();
        if (it < 13) ISSUE((it + 3) & 3, (it + 3) * 32);
        CP_COMMIT;

        const int s = it & 3;
#pragma unroll
        for (int ks = 0; ks < 32; ks += 16) {
            uint32_t af[4][4], bf[4][2];
#pragma unroll
            for (int mt = 0; mt < 4; mt++) {
                const int r = wm + (mt << 4) + g;
                af[mt][0] = *(const uint32_t*)&As[s][r][ks + 2 * tg];
                af[mt][1] = *(const uint32_t*)&As[s][r + 8][ks + 2 * tg];
                af[mt][2] = *(const uint32_t*)&As[s][r][ks + 2 * tg + 8];
                af[mt][3] = *(const uint32_t*)&As[s][r + 8][ks + 2 * tg + 8];
            }
#pragma unroll
            for (int nt = 0; nt < 4; nt++) {
                const int r = wn + (nt << 3) + g;
                bf[nt][0] = *(const uint32_t*)&Bs[s][r][ks + 2 * tg];
                bf[nt][1] = *(const uint32_t*)&Bs[s][r][ks + 2 * tg + 8];
            }
#pragma unroll
            for (int mt = 0; mt < 4; mt++)
#pragma unroll
                for (int nt = 0; nt < 4; nt++) {
                    asm volatile(
                        "mma.sync.aligned.m16n8k16.row.col.f32.f16.f16.f32 "
                        "{%0,%1,%2,%3}, {%4,%5,%6,%7}, {%8,%9}, {%0,%1,%2,%3};"
                        : "+f"(acc[mt][nt][0]), "+f"(acc[mt][nt][1]),
                          "+f"(acc[mt][nt][2]), "+f"(acc[mt][nt][3])
                        : "r"(af[mt][0]), "r"(af[mt][1]),
                          "r"(af[mt][2]), "r"(af[mt][3]),
                          "r"(bf[nt][0]), "r"(bf[nt][1]));
                }
        }
    }
#undef ISSUE

    // Epilogue: add bias, store.
#pragma unroll
    for (int nt = 0; nt < 4; nt++) {
        const int n = n0 + wn + (nt << 3) + (tg << 1);
        const float b0v = bias[n];
        const float b1v = bias[n + 1];
#pragma unroll
        for (int mt = 0; mt < 4; mt++) {
            const int m = m0 + wm + (mt << 4) + g;
            float2 v0 = make_float2(acc[mt][nt][0] + b0v, acc[mt][nt][1] + b1v);
            float2 v1 = make_float2(acc[mt][nt][2] + b0v, acc[mt][nt][3] + b1v);
            *(float2*)&g_wf[m * CC + n]       = v0;
            *(float2*)&g_wf[(m + 8) * CC + n] = v1;
        }
    }
}

// ---------------------------------------------------------------------------
// Kernel B1 v5: scores[b,l,t] = sum_c tanh(wf[b,t,c]+pos[l,c])*aw[c] + ab
// Hybrid tanh: 10/16 elements via MUFU.TANH (rt16), 6/16 via rational poly
// on the FMA pipe -> balances the two pipes (~13 cyc/elem vs 16 pure MUFU).
// One warp per FOUR t-rows. grid = (T/32, B), 256 threads.
// ---------------------------------------------------------------------------
__global__ __launch_bounds__(256) void scores_kernel(
    const float* __restrict__ pos_emb,   // [25, 512]
    const float* __restrict__ atten_w,   // [512]
    const float* __restrict__ atten_b)   // [1]
{
    const int warp = threadIdx.x >> 5;
    const int lane = threadIdx.x & 31;
    const int b = blockIdx.y;
    const int t0 = blockIdx.x * 32 + warp * 4;

    const float4* awr = (const float4*)atten_w;

    float4 wf[4][4], aw4[4];
#pragma unroll
    for (int r = 0; r < 4; r++) {
        const float4* wfr = (const float4*)(g_wf + (b * TT + t0 + r) * CC);
#pragma unroll
        for (int i = 0; i < 4; i++) wf[r][i] = wfr[lane + 32 * i];
    }
#pragma unroll
    for (int i = 0; i < 4; i++) aw4[i] = awr[lane + 32 * i];
    const float bsc = atten_b[0];

#pragma unroll 1
    for (int l = 0; l < LL; l++) {
        const float4* pr = (const float4*)(pos_emb + l * CC);
        float acc0 = 0.f, acc1 = 0.f, acc2 = 0.f, acc3 = 0.f;
#pragma unroll
        for (int i = 0; i < 4; i++) {
            float4 p = __ldg(&pr[lane + 32 * i]);
            const bool zmufu = (i & 1) == 0;  // compile-time under unroll
            // row 0
            acc0 = fmaf(htanh(wf[0][i].x + p.x), aw4[i].x, acc0);
            acc0 = fmaf(htanh(wf[0][i].y + p.y), aw4[i].y, acc0);
            acc0 = fmaf(zmufu ? htanh(wf[0][i].z + p.z)
                              : tanh_poly(wf[0][i].z + p.z), aw4[i].z, acc0);
            acc0 = fmaf(tanh_poly(wf[0][i].w + p.w), aw4[i].w, acc0);
            // row 1
            acc1 = fmaf(htanh(wf[1][i].x + p.x), aw4[i].x, acc1);
            acc1 = fmaf(htanh(wf[1][i].y + p.y), aw4[i].y, acc1);
            acc1 = fmaf(zmufu ? htanh(wf[1][i].z + p.z)
                              : tanh_poly(wf[1][i].z + p.z), aw4[i].z, acc1);
            acc1 = fmaf(tanh_poly(wf[1][i].w + p.w), aw4[i].w, acc1);
            // row 2
            acc2 = fmaf(htanh(wf[2][i].x + p.x), aw4[i].x, acc2);
            acc2 = fmaf(htanh(wf[2][i].y + p.y), aw4[i].y, acc2);
            acc2 = fmaf(zmufu ? htanh(wf[2][i].z + p.z)
                              : tanh_poly(wf[2][i].z + p.z), aw4[i].z, acc2);
            acc2 = fmaf(tanh_poly(wf[2][i].w + p.w), aw4[i].w, acc2);
            // row 3
            acc3 = fmaf(htanh(wf[3][i].x + p.x), aw4[i].x, acc3);
            acc3 = fmaf(htanh(wf[3][i].y + p.y), aw4[i].y, acc3);
            acc3 = fmaf(zmufu ? htanh(wf[3][i].z + p.z)
                              : tanh_poly(wf[3][i].z + p.z), aw4[i].z, acc3);
            acc3 = fmaf(tanh_poly(wf[3][i].w + p.w), aw4[i].w, acc3);
        }
#pragma unroll
        for (int s = 16; s; s >>= 1) {
            acc0 += __shfl_xor_sync(0xffffffffu, acc0, s);
            acc1 += __shfl_xor_sync(0xffffffffu, acc1, s);
            acc2 += __shfl_xor_sync(0xffffffffu, acc2, s);
            acc3 += __shfl_xor_sync(0xffffffffu, acc3, s);
        }
        if (lane == 0) {
            *(float4*)&g_scores[(b * LL + l) * TT + t0] =
                make_float4(acc0 + bsc, acc1 + bsc, acc2 + bsc, acc3 + bsc);
        }
    }
}

// ---------------------------------------------------------------------------
// Kernel B2: softmax over t, then pvam[b,l,c] = sum_t attn[l,t]*wf[b,t,c]
// ---------------------------------------------------------------------------
__global__ __launch_bounds__(256) void pvam_kernel(float* __restrict__ out)
{
    __shared__ float attn_s[LL * TT];  // 25.6 KB
    const int b = blockIdx.y;
    const int tid = threadIdx.x;
    const int warp = tid >> 5;
    const int lane = tid & 31;

    for (int l = warp; l < LL; l += 8) {
        const float* sr = g_scores + (b * LL + l) * TT;
        float v[8];
        float m = -1e30f;
#pragma unroll
        for (int i = 0; i < 8; i++) {
            v[i] = sr[lane + 32 * i];
            m = fmaxf(m, v[i]);
        }
#pragma unroll
        for (int s = 16; s; s >>= 1) m = fmaxf(m, __shfl_xor_sync(0xffffffffu, m, s));
        float ssum = 0.f;
#pragma unroll
        for (int i = 0; i < 8; i++) {
            float e = __expf(v[i] - m);
            attn_s[l * TT + lane + 32 * i] = e;
            ssum += e;
        }
#pragma unroll
        for (int s = 16; s; s >>= 1) ssum += __shfl_xor_sync(0xffffffffu, ssum, s);
        float inv = __fdividef(1.f, ssum);
#pragma unroll
        for (int i = 0; i < 8; i++) attn_s[l * TT + lane + 32 * i] *= inv;
    }
    __syncthreads();

    const int c = blockIdx.x * 256 + tid;
    const float* wfb = g_wf + (b * TT) * CC + c;
    float acc[LL];
#pragma unroll
    for (int l = 0; l < LL; l++) acc[l] = 0.f;

    for (int t4 = 0; t4 < TT; t4 += 4) {
        float w0 = wfb[(t4 + 0) * CC];
        float w1 = wfb[(t4 + 1) * CC];
        float w2 = wfb[(t4 + 2) * CC];
        float w3 = wfb[(t4 + 3) * CC];
#pragma unroll
        for (int l = 0; l < LL; l++) {
            float4 a = *(const float4*)&attn_s[l * TT + t4];
            float s0 = fmaf(a.x, w0, acc[l]);
            float s1 = fmaf(a.y, w1, s0);
            float s2 = fmaf(a.z, w2, s1);
            acc[l] = fmaf(a.w, w3, s2);
        }
    }

    float* o = out + (b * LL) * CC + c;
#pragma unroll
    for (int l = 0; l < LL; l++) o[l * CC] = acc[l];
}

// ---------------------------------------------------------------------------
extern "C" void kernel_launch(void* const* d_in, const int* in_sizes, int n_in,
                              void* d_out, int out_size)
{
    const float* word_features = (const float*)d_in[0];  // (32,256,512)
    const float* word_fc_w     = (const float*)d_in[1];  // (512,512)
    const float* word_fc_b     = (const float*)d_in[2];  // (512,)
    const float* pos_emb       = (const float*)d_in[3];  // (25,512)
    const float* atten_w       = (const float*)d_in[4];  // (512,)
    const float* atten_b       = (const float*)d_in[5];  // (1,)
    float* out = (float*)d_out;                          // (32,25,512)

    const int smem_bytes = 2 * A_HALVES * 2;  // 81920
    cudaFuncSetAttribute(wf_gemm_pipe,
                         cudaFuncAttributeMaxDynamicSharedMemorySize, smem_bytes);

    const int NCV = (BB * TT * CC + CC * CC) / 4;
    cvt_to_half<<<(NCV + 255) / 256, 256>>>(word_features, word_fc_w);
    wf_gemm_pipe<<<dim3(CC / 128, (BB * TT) / 128), 256, smem_bytes>>>(word_fc_b);
    scores_kernel<<<dim3(TT / 32, BB), 256>>>(pos_emb, atten_w, atten_b);
    pvam_kernel<<<dim3(CC / 256, BB), 256>>>(out);
}

// round 12
// speedup vs baseline: 1.5550x; 1.3548x over previous
#include <cuda_runtime.h>
#include <cuda_fp16.h>
#include <cuda_bf16.h>
#include <cstdint>

// Problem constants (fixed by reference)
#define BB 32
#define TT 256
#define CC 512
#define LL 25
#define TSPLIT 4
#define TCH (TT / TSPLIT)   // 64

// Scratch in device globals (no allocations allowed in kernel_launch)
__device__ float g_wf[BB * TT * CC];                 // 16 MB: post-FC features
__device__ float g_scores[BB * LL * TT];             // 0.8 MB: logits
__device__ float g_attn[BB * LL * TT];               // 0.8 MB: softmaxed attn
__device__ float g_part[TSPLIT * BB * LL * CC];      // 6.5 MB: pvam partials

// ---------------------------------------------------------------------------
__device__ __forceinline__ __half2 htanh2(__half2 x) {
    uint32_t xu = *(uint32_t*)&x, yu;
    asm("tanh.approx.f16x2 %0, %1;" : "=r"(yu) : "r"(xu));
    return *(__half2*)&yu;
}
__device__ __forceinline__ __half2 packh2(float lo, float hi) {
    return __float22half2_rn(make_float2(lo, hi));
}

// ---------------------------------------------------------------------------
// Kernel A: wf[m,n] = sum_k X[m,k] * W[n,k] + bias[n]
// fp16 mma m16n8k16, fp32 accum. Block 128x128, BK=16, double-buffered.
// (R5 version — measured 32.8us)
// ---------------------------------------------------------------------------
#define PADH 24
__global__ __launch_bounds__(256, 2) void wf_gemm_fp16(
    const float* __restrict__ X,     // [8192, 512]
    const float* __restrict__ W,     // [512, 512] (row n, col k)
    const float* __restrict__ bias)  // [512]
{
    __shared__ __half As[2][128][PADH];
    __shared__ __half Bs[2][128][PADH];

    const int tid  = threadIdx.x;
    const int lane = tid & 31;
    const int warp = tid >> 5;
    const int g    = lane >> 2;
    const int tg   = lane & 3;
    const int wm   = (warp >> 2) << 6;
    const int wn   = (warp & 3) << 5;

    const int m0 = blockIdx.y << 7;
    const int n0 = blockIdx.x << 7;

    const int lr = tid >> 2;
    const int lc = (tid & 3) << 2;

    const float* Ag = X + (m0 + lr) * CC + lc;
    const float* Bg = W + (n0 + lr) * CC + lc;

    float acc[4][4][4];
#pragma unroll
    for (int mt = 0; mt < 4; mt++)
#pragma unroll
        for (int nt = 0; nt < 4; nt++)
#pragma unroll
            for (int i = 0; i < 4; i++) acc[mt][nt][i] = 0.f;

    float4 pa0, pa1, pb0, pb1;

#define CVT_STORE(dst, v)                                                     \
    do {                                                                      \
        __half2 h0 = __float22half2_rn(make_float2((v).x, (v).y));            \
        __half2 h1 = __float22half2_rn(make_float2((v).z, (v).w));            \
        *(uint2*)(dst) = make_uint2(*(uint32_t*)&h0, *(uint32_t*)&h1);        \
    } while (0)

#define GEMM_STORE_TILE(SS)                                                   \
    do {                                                                      \
        CVT_STORE(&As[SS][lr][lc], pa0);                                      \
        CVT_STORE(&As[SS][lr + 64][lc], pa1);                                 \
        CVT_STORE(&Bs[SS][lr][lc], pb0);                                      \
        CVT_STORE(&Bs[SS][lr + 64][lc], pb1);                                 \
    } while (0)

    pa0 = *(const float4*)(Ag);
    pa1 = *(const float4*)(Ag + 64 * CC);
    pb0 = *(const float4*)(Bg);
    pb1 = *(const float4*)(Bg + 64 * CC);
    GEMM_STORE_TILE(0);
    __syncthreads();

    int s = 0;
    for (int it = 0; it < 32; ++it) {
        if (it < 31) {
            const int ko = (it + 1) << 4;
            pa0 = *(const float4*)(Ag + ko);
            pa1 = *(const float4*)(Ag + 64 * CC + ko);
            pb0 = *(const float4*)(Bg + ko);
            pb1 = *(const float4*)(Bg + 64 * CC + ko);
        }
        {
            uint32_t af[4][4], bf[4][2];
#pragma unroll
            for (int mt = 0; mt < 4; mt++) {
                const int r = wm + (mt << 4) + g;
                af[mt][0] = *(const uint32_t*)&As[s][r][2 * tg];
                af[mt][1] = *(const uint32_t*)&As[s][r + 8][2 * tg];
                af[mt][2] = *(const uint32_t*)&As[s][r][2 * tg + 8];
                af[mt][3] = *(const uint32_t*)&As[s][r + 8][2 * tg + 8];
            }
#pragma unroll
            for (int nt = 0; nt < 4; nt++) {
                const int r = wn + (nt << 3) + g;
                bf[nt][0] = *(const uint32_t*)&Bs[s][r][2 * tg];
                bf[nt][1] = *(const uint32_t*)&Bs[s][r][2 * tg + 8];
            }
#pragma unroll
            for (int mt = 0; mt < 4; mt++)
#pragma unroll
                for (int nt = 0; nt < 4; nt++) {
                    asm volatile(
                        "mma.sync.aligned.m16n8k16.row.col.f32.f16.f16.f32 "
                        "{%0,%1,%2,%3}, {%4,%5,%6,%7}, {%8,%9}, {%0,%1,%2,%3};"
                        : "+f"(acc[mt][nt][0]), "+f"(acc[mt][nt][1]),
                          "+f"(acc[mt][nt][2]), "+f"(acc[mt][nt][3])
                        : "r"(af[mt][0]), "r"(af[mt][1]),
                          "r"(af[mt][2]), "r"(af[mt][3]),
                          "r"(bf[nt][0]), "r"(bf[nt][1]));
                }
        }
        if (it < 31) {
            const int ns = s ^ 1;
            GEMM_STORE_TILE(ns);
            __syncthreads();
            s = ns;
        }
    }

#pragma unroll
    for (int nt = 0; nt < 4; nt++) {
        const int n = n0 + wn + (nt << 3) + (tg << 1);
        const float b0v = bias[n];
        const float b1v = bias[n + 1];
#pragma unroll
        for (int mt = 0; mt < 4; mt++) {
            const int m = m0 + wm + (mt << 4) + g;
            float2 v0 = make_float2(acc[mt][nt][0] + b0v, acc[mt][nt][1] + b1v);
            float2 v1 = make_float2(acc[mt][nt][2] + b0v, acc[mt][nt][3] + b1v);
            *(float2*)&g_wf[m * CC + n]       = v0;
            *(float2*)&g_wf[(m + 8) * CC + n] = v1;
        }
    }
#undef GEMM_STORE_TILE
#undef CVT_STORE
}

// ---------------------------------------------------------------------------
// Kernel B1: scores[b,l,t] (R5 f16x2 version — measured ~11us)
// ---------------------------------------------------------------------------
__global__ __launch_bounds__(256) void scores_kernel(
    const float* __restrict__ pos_emb,   // [25, 512]
    const float* __restrict__ atten_w,   // [512]
    const float* __restrict__ atten_b)   // [1]
{
    const int warp = threadIdx.x >> 5;
    const int lane = threadIdx.x & 31;
    const int b = blockIdx.y;
    const int t0 = blockIdx.x * 32 + warp * 4;

    const float4* awr = (const float4*)atten_w;

    __half2 wfh[4][8];
    float4 aw4[4];
#pragma unroll
    for (int r = 0; r < 4; r++) {
        const float4* wfr = (const float4*)(g_wf + (b * TT + t0 + r) * CC);
#pragma unroll
        for (int i = 0; i < 4; i++) {
            float4 v = wfr[lane + 32 * i];
            wfh[r][2 * i]     = packh2(v.x, v.y);
            wfh[r][2 * i + 1] = packh2(v.z, v.w);
        }
    }
#pragma unroll
    for (int i = 0; i < 4; i++) aw4[i] = awr[lane + 32 * i];
    const float bsc = atten_b[0];

#pragma unroll 2
    for (int l = 0; l < LL; l++) {
        const float4* pr = (const float4*)(pos_emb + l * CC);
        float acc0 = 0.f, acc1 = 0.f, acc2 = 0.f, acc3 = 0.f;
#pragma unroll
        for (int i = 0; i < 4; i++) {
            float4 p = __ldg(&pr[lane + 32 * i]);
            __half2 p01 = packh2(p.x, p.y);
            __half2 p23 = packh2(p.z, p.w);

            __half2 tA0 = htanh2(__hadd2(wfh[0][2 * i], p01));
            __half2 tA1 = htanh2(__hadd2(wfh[0][2 * i + 1], p23));
            __half2 tB0 = htanh2(__hadd2(wfh[1][2 * i], p01));
            __half2 tB1 = htanh2(__hadd2(wfh[1][2 * i + 1], p23));
            __half2 tC0 = htanh2(__hadd2(wfh[2][2 * i], p01));
            __half2 tC1 = htanh2(__hadd2(wfh[2][2 * i + 1], p23));
            __half2 tD0 = htanh2(__hadd2(wfh[3][2 * i], p01));
            __half2 tD1 = htanh2(__hadd2(wfh[3][2 * i + 1], p23));

            acc0 = fmaf(__low2float(tA0),  aw4[i].x, acc0);
            acc0 = fmaf(__high2float(tA0), aw4[i].y, acc0);
            acc0 = fmaf(__low2float(tA1),  aw4[i].z, acc0);
            acc0 = fmaf(__high2float(tA1), aw4[i].w, acc0);
            acc1 = fmaf(__low2float(tB0),  aw4[i].x, acc1);
            acc1 = fmaf(__high2float(tB0), aw4[i].y, acc1);
            acc1 = fmaf(__low2float(tB1),  aw4[i].z, acc1);
            acc1 = fmaf(__high2float(tB1), aw4[i].w, acc1);
            acc2 = fmaf(__low2float(tC0),  aw4[i].x, acc2);
            acc2 = fmaf(__high2float(tC0), aw4[i].y, acc2);
            acc2 = fmaf(__low2float(tC1),  aw4[i].z, acc2);
            acc2 = fmaf(__high2float(tC1), aw4[i].w, acc2);
            acc3 = fmaf(__low2float(tD0),  aw4[i].x, acc3);
            acc3 = fmaf(__high2float(tD0), aw4[i].y, acc3);
            acc3 = fmaf(__low2float(tD1),  aw4[i].z, acc3);
            acc3 = fmaf(__high2float(tD1), aw4[i].w, acc3);
        }
#pragma unroll
        for (int s = 16; s; s >>= 1) {
            acc0 += __shfl_xor_sync(0xffffffffu, acc0, s);
            acc1 += __shfl_xor_sync(0xffffffffu, acc1, s);
            acc2 += __shfl_xor_sync(0xffffffffu, acc2, s);
            acc3 += __shfl_xor_sync(0xffffffffu, acc3, s);
        }
        if (lane == 0) {
            *(float4*)&g_scores[(b * LL + l) * TT + t0] =
                make_float4(acc0 + bsc, acc1 + bsc, acc2 + bsc, acc3 + bsc);
        }
    }
}

// ---------------------------------------------------------------------------
// Kernel B2a: softmax over t per (b,l), writes normalized attn to global.
// grid = B (32), 256 threads: one warp per l (looped).
// ---------------------------------------------------------------------------
__global__ __launch_bounds__(256) void softmax_kernel()
{
    const int b = blockIdx.x;
    const int warp = threadIdx.x >> 5;
    const int lane = threadIdx.x & 31;

    for (int l = warp; l < LL; l += 8) {
        const float* sr = g_scores + (b * LL + l) * TT;
        float* ar = g_attn + (b * LL + l) * TT;
        float v[8];
        float m = -1e30f;
#pragma unroll
        for (int i = 0; i < 8; i++) {
            v[i] = sr[lane + 32 * i];
            m = fmaxf(m, v[i]);
        }
#pragma unroll
        for (int s = 16; s; s >>= 1) m = fmaxf(m, __shfl_xor_sync(0xffffffffu, m, s));
        float ssum = 0.f;
#pragma unroll
        for (int i = 0; i < 8; i++) {
            v[i] = __expf(v[i] - m);
            ssum += v[i];
        }
#pragma unroll
        for (int s = 16; s; s >>= 1) ssum += __shfl_xor_sync(0xffffffffu, ssum, s);
        float inv = __fdividef(1.f, ssum);
#pragma unroll
        for (int i = 0; i < 8; i++) ar[lane + 32 * i] = v[i] * inv;
    }
}

// ---------------------------------------------------------------------------
// Kernel B2b: partial pvam over a 64-t chunk.
// grid = (C/256, B, TSPLIT) = (2, 32, 4) = 256 CTAs — full-chip parallelism.
// part[tz,b,l,c] = sum_{t in chunk} attn[b,l,t] * wf[b,t,c]
// ---------------------------------------------------------------------------
__global__ __launch_bounds__(256) void pvam_part_kernel()
{
    __shared__ float attn_s[LL * TCH];   // 25*64 floats = 6.4 KB
    const int tid = threadIdx.x;
    const int b  = blockIdx.y;
    const int tz = blockIdx.z;

    // load attn chunk [25][64]
    for (int idx = tid; idx < LL * TCH; idx += 256) {
        const int l = idx / TCH;
        const int t = idx - l * TCH;
        attn_s[idx] = g_attn[(b * LL + l) * TT + tz * TCH + t];
    }
    __syncthreads();

    const int c = blockIdx.x * 256 + tid;
    const float* wfb = g_wf + (b * TT + tz * TCH) * CC + c;

    float acc[LL];
#pragma unroll
    for (int l = 0; l < LL; l++) acc[l] = 0.f;

    for (int t4 = 0; t4 < TCH; t4 += 4) {
        float w0 = wfb[(t4 + 0) * CC];
        float w1 = wfb[(t4 + 1) * CC];
        float w2 = wfb[(t4 + 2) * CC];
        float w3 = wfb[(t4 + 3) * CC];
#pragma unroll
        for (int l = 0; l < LL; l++) {
            float4 a = *(const float4*)&attn_s[l * TCH + t4];
            float s0 = fmaf(a.x, w0, acc[l]);
            float s1 = fmaf(a.y, w1, s0);
            float s2 = fmaf(a.z, w2, s1);
            acc[l] = fmaf(a.w, w3, s2);
        }
    }

    float* o = g_part + ((tz * BB + b) * LL) * CC + c;
#pragma unroll
    for (int l = 0; l < LL; l++) o[l * CC] = acc[l];
}

// ---------------------------------------------------------------------------
// Kernel B2c: reduce TSPLIT partials -> out. 409600 floats = 102400 float4.
// ---------------------------------------------------------------------------
__global__ __launch_bounds__(256) void pvam_reduce_kernel(float* __restrict__ out)
{
    const int i = blockIdx.x * 256 + threadIdx.x;      // float4 index
    const int STRIDE4 = BB * LL * CC / 4;              // 102400
    const float4* p = (const float4*)g_part;
    float4 a = p[i];
    float4 b = p[i + STRIDE4];
    float4 c = p[i + 2 * STRIDE4];
    float4 d = p[i + 3 * STRIDE4];
    float4 r;
    r.x = (a.x + b.x) + (c.x + d.x);
    r.y = (a.y + b.y) + (c.y + d.y);
    r.z = (a.z + b.z) + (c.z + d.z);
    r.w = (a.w + b.w) + (c.w + d.w);
    ((float4*)out)[i] = r;
}

// ---------------------------------------------------------------------------
extern "C" void kernel_launch(void* const* d_in, const int* in_sizes, int n_in,
                              void* d_out, int out_size)
{
    const float* word_features = (const float*)d_in[0];  // (32,256,512)
    const float* word_fc_w     = (const float*)d_in[1];  // (512,512)
    const float* word_fc_b     = (const float*)d_in[2];  // (512,)
    const float* pos_emb       = (const float*)d_in[3];  // (25,512)
    const float* atten_w       = (const float*)d_in[4];  // (512,)
    const float* atten_b       = (const float*)d_in[5];  // (1,)
    float* out = (float*)d_out;                          // (32,25,512)

    wf_gemm_fp16<<<dim3(CC / 128, (BB * TT) / 128), 256>>>(
        word_features, word_fc_w, word_fc_b);
    scores_kernel<<<dim3(TT / 32, BB), 256>>>(pos_emb, atten_w, atten_b);
    softmax_kernel<<<BB, 256>>>();
    pvam_part_kernel<<<dim3(CC / 256, BB, TSPLIT), 256>>>();
    pvam_reduce_kernel<<<(BB * LL * CC / 4) / 256, 256>>>(out);
}

// round 13
// speedup vs baseline: 1.7217x; 1.1072x over previous
#include <cuda_runtime.h>
#include <cuda_fp16.h>
#include <cuda_bf16.h>
#include <cstdint>

// Problem constants (fixed by reference)
#define BB 32
#define TT 256
#define CC 512
#define LL 25
#define TSPLIT 8
#define TCH (TT / TSPLIT)   // 32
#define CC2 (CC / 2)        // 256 half2 per row

// Scratch in device globals (no allocations allowed in kernel_launch)
__device__ __half g_wfh[BB * TT * CC];               // 8 MB: post-FC features (fp16)
__device__ float  g_scores[BB * LL * TT];            // 0.8 MB: logits
__device__ float  g_part[TSPLIT * BB * LL * CC];     // 13.1 MB: pvam partials

// ---------------------------------------------------------------------------
__device__ __forceinline__ __half2 htanh2(__half2 x) {
    uint32_t xu = *(uint32_t*)&x, yu;
    asm("tanh.approx.f16x2 %0, %1;" : "=r"(yu) : "r"(xu));
    return *(__half2*)&yu;
}
__device__ __forceinline__ __half2 packh2(float lo, float hi) {
    return __float22half2_rn(make_float2(lo, hi));
}

// ---------------------------------------------------------------------------
// Kernel A: wf[m,n] = sum_k X[m,k]*W[n,k] + bias[n], stored as fp16.
// fp16 mma m16n8k16, fp32 accum. Block 128x128, BK=16, double-buffered.
// ---------------------------------------------------------------------------
#define PADH 24
__global__ __launch_bounds__(256, 2) void wf_gemm_fp16(
    const float* __restrict__ X,     // [8192, 512]
    const float* __restrict__ W,     // [512, 512] (row n, col k)
    const float* __restrict__ bias)  // [512]
{
    __shared__ __half As[2][128][PADH];
    __shared__ __half Bs[2][128][PADH];

    const int tid  = threadIdx.x;
    const int lane = tid & 31;
    const int warp = tid >> 5;
    const int g    = lane >> 2;
    const int tg   = lane & 3;
    const int wm   = (warp >> 2) << 6;
    const int wn   = (warp & 3) << 5;

    const int m0 = blockIdx.y << 7;
    const int n0 = blockIdx.x << 7;

    const int lr = tid >> 2;
    const int lc = (tid & 3) << 2;

    const float* Ag = X + (m0 + lr) * CC + lc;
    const float* Bg = W + (n0 + lr) * CC + lc;

    float acc[4][4][4];
#pragma unroll
    for (int mt = 0; mt < 4; mt++)
#pragma unroll
        for (int nt = 0; nt < 4; nt++)
#pragma unroll
            for (int i = 0; i < 4; i++) acc[mt][nt][i] = 0.f;

    float4 pa0, pa1, pb0, pb1;

#define CVT_STORE(dst, v)                                                     \
    do {                                                                      \
        __half2 h0 = __float22half2_rn(make_float2((v).x, (v).y));            \
        __half2 h1 = __float22half2_rn(make_float2((v).z, (v).w));            \
        *(uint2*)(dst) = make_uint2(*(uint32_t*)&h0, *(uint32_t*)&h1);        \
    } while (0)

#define GEMM_STORE_TILE(SS)                                                   \
    do {                                                                      \
        CVT_STORE(&As[SS][lr][lc], pa0);                                      \
        CVT_STORE(&As[SS][lr + 64][lc], pa1);                                 \
        CVT_STORE(&Bs[SS][lr][lc], pb0);                                      \
        CVT_STORE(&Bs[SS][lr + 64][lc], pb1);                                 \
    } while (0)

    pa0 = *(const float4*)(Ag);
    pa1 = *(const float4*)(Ag + 64 * CC);
    pb0 = *(const float4*)(Bg);
    pb1 = *(const float4*)(Bg + 64 * CC);
    GEMM_STORE_TILE(0);
    __syncthreads();

    int s = 0;
    for (int it = 0; it < 32; ++it) {
        if (it < 31) {
            const int ko = (it + 1) << 4;
            pa0 = *(const float4*)(Ag + ko);
            pa1 = *(const float4*)(Ag + 64 * CC + ko);
            pb0 = *(const float4*)(Bg + ko);
            pb1 = *(const float4*)(Bg + 64 * CC + ko);
        }
        {
            uint32_t af[4][4], bf[4][2];
#pragma unroll
            for (int mt = 0; mt < 4; mt++) {
                const int r = wm + (mt << 4) + g;
                af[mt][0] = *(const uint32_t*)&As[s][r][2 * tg];
                af[mt][1] = *(const uint32_t*)&As[s][r + 8][2 * tg];
                af[mt][2] = *(const uint32_t*)&As[s][r][2 * tg + 8];
                af[mt][3] = *(const uint32_t*)&As[s][r + 8][2 * tg + 8];
            }
#pragma unroll
            for (int nt = 0; nt < 4; nt++) {
                const int r = wn + (nt << 3) + g;
                bf[nt][0] = *(const uint32_t*)&Bs[s][r][2 * tg];
                bf[nt][1] = *(const uint32_t*)&Bs[s][r][2 * tg + 8];
            }
#pragma unroll
            for (int mt = 0; mt < 4; mt++)
#pragma unroll
                for (int nt = 0; nt < 4; nt++) {
                    asm volatile(
                        "mma.sync.aligned.m16n8k16.row.col.f32.f16.f16.f32 "
                        "{%0,%1,%2,%3}, {%4,%5,%6,%7}, {%8,%9}, {%0,%1,%2,%3};"
                        : "+f"(acc[mt][nt][0]), "+f"(acc[mt][nt][1]),
                          "+f"(acc[mt][nt][2]), "+f"(acc[mt][nt][3])
                        : "r"(af[mt][0]), "r"(af[mt][1]),
                          "r"(af[mt][2]), "r"(af[mt][3]),
                          "r"(bf[nt][0]), "r"(bf[nt][1]));
                }
        }
        if (it < 31) {
            const int ns = s ^ 1;
            GEMM_STORE_TILE(ns);
            __syncthreads();
            s = ns;
        }
    }

    // Epilogue: add bias, convert to fp16, store (half the bytes of fp32).
#pragma unroll
    for (int nt = 0; nt < 4; nt++) {
        const int n = n0 + wn + (nt << 3) + (tg << 1);
        const float b0v = bias[n];
        const float b1v = bias[n + 1];
#pragma unroll
        for (int mt = 0; mt < 4; mt++) {
            const int m = m0 + wm + (mt << 4) + g;
            __half2 h0 = packh2(acc[mt][nt][0] + b0v, acc[mt][nt][1] + b1v);
            __half2 h1 = packh2(acc[mt][nt][2] + b0v, acc[mt][nt][3] + b1v);
            *(__half2*)&g_wfh[m * CC + n]       = h0;
            *(__half2*)&g_wfh[(m + 8) * CC + n] = h1;
        }
    }
#undef GEMM_STORE_TILE
#undef CVT_STORE
}

// ---------------------------------------------------------------------------
// Kernel B1: scores[b,l,t] = sum_c tanh(wf+pos)*aw + ab  (reads fp16 wf —
// numerically identical to prior version: same _rn rounding, now upstream).
// One warp per FOUR t-rows. grid = (T/32, B), 256 threads.
// ---------------------------------------------------------------------------
__global__ __launch_bounds__(256) void scores_kernel(
    const float* __restrict__ pos_emb,   // [25, 512]
    const float* __restrict__ atten_w,   // [512]
    const float* __restrict__ atten_b)   // [1]
{
    const int warp = threadIdx.x >> 5;
    const int lane = threadIdx.x & 31;
    const int b = blockIdx.y;
    const int t0 = blockIdx.x * 32 + warp * 4;

    const float4* awr = (const float4*)atten_w;

    __half2 wfh[4][8];
    float4 aw4[4];
#pragma unroll
    for (int r = 0; r < 4; r++) {
        const uint2* wfr = (const uint2*)(g_wfh + (b * TT + t0 + r) * CC);
#pragma unroll
        for (int i = 0; i < 4; i++) {
            uint2 u = wfr[lane + 32 * i];   // 4 halves at c = 4*(lane+32i)
            wfh[r][2 * i]     = *(__half2*)&u.x;
            wfh[r][2 * i + 1] = *(__half2*)&u.y;
        }
    }
#pragma unroll
    for (int i = 0; i < 4; i++) aw4[i] = awr[lane + 32 * i];
    const float bsc = atten_b[0];

#pragma unroll 2
    for (int l = 0; l < LL; l++) {
        const float4* pr = (const float4*)(pos_emb + l * CC);
        float acc0 = 0.f, acc1 = 0.f, acc2 = 0.f, acc3 = 0.f;
#pragma unroll
        for (int i = 0; i < 4; i++) {
            float4 p = __ldg(&pr[lane + 32 * i]);
            __half2 p01 = packh2(p.x, p.y);
            __half2 p23 = packh2(p.z, p.w);

            __half2 tA0 = htanh2(__hadd2(wfh[0][2 * i], p01));
            __half2 tA1 = htanh2(__hadd2(wfh[0][2 * i + 1], p23));
            __half2 tB0 = htanh2(__hadd2(wfh[1][2 * i], p01));
            __half2 tB1 = htanh2(__hadd2(wfh[1][2 * i + 1], p23));
            __half2 tC0 = htanh2(__hadd2(wfh[2][2 * i], p01));
            __half2 tC1 = htanh2(__hadd2(wfh[2][2 * i + 1], p23));
            __half2 tD0 = htanh2(__hadd2(wfh[3][2 * i], p01));
            __half2 tD1 = htanh2(__hadd2(wfh[3][2 * i + 1], p23));

            acc0 = fmaf(__low2float(tA0),  aw4[i].x, acc0);
            acc0 = fmaf(__high2float(tA0), aw4[i].y, acc0);
            acc0 = fmaf(__low2float(tA1),  aw4[i].z, acc0);
            acc0 = fmaf(__high2float(tA1), aw4[i].w, acc0);
            acc1 = fmaf(__low2float(tB0),  aw4[i].x, acc1);
            acc1 = fmaf(__high2float(tB0), aw4[i].y, acc1);
            acc1 = fmaf(__low2float(tB1),  aw4[i].z, acc1);
            acc1 = fmaf(__high2float(tB1), aw4[i].w, acc1);
            acc2 = fmaf(__low2float(tC0),  aw4[i].x, acc2);
            acc2 = fmaf(__high2float(tC0), aw4[i].y, acc2);
            acc2 = fmaf(__low2float(tC1),  aw4[i].z, acc2);
            acc2 = fmaf(__high2float(tC1), aw4[i].w, acc2);
            acc3 = fmaf(__low2float(tD0),  aw4[i].x, acc3);
            acc3 = fmaf(__high2float(tD0), aw4[i].y, acc3);
            acc3 = fmaf(__low2float(tD1),  aw4[i].z, acc3);
            acc3 = fmaf(__high2float(tD1), aw4[i].w, acc3);
        }
#pragma unroll
        for (int s = 16; s; s >>= 1) {
            acc0 += __shfl_xor_sync(0xffffffffu, acc0, s);
            acc1 += __shfl_xor_sync(0xffffffffu, acc1, s);
            acc2 += __shfl_xor_sync(0xffffffffu, acc2, s);
            acc3 += __shfl_xor_sync(0xffffffffu, acc3, s);
        }
        if (lane == 0) {
            *(float4*)&g_scores[(b * LL + l) * TT + t0] =
                make_float4(acc0 + bsc, acc1 + bsc, acc2 + bsc, acc3 + bsc);
        }
    }
}

// ---------------------------------------------------------------------------
// Kernel B2a: partial pvam over a 32-t chunk, softmax inlined (each CTA
// redundantly softmaxes its b's 25x256 score block in smem — cheap).
// grid = (B, TSPLIT) = 256 CTAs. Thread owns one half2 column (c2 = tid).
// part[tz,b,l,c] = sum_{t in chunk} attn[b,l,t] * wf16[b,t,c]
// ---------------------------------------------------------------------------
__global__ __launch_bounds__(256) void pvam_part_kernel()
{
    __shared__ float at[LL * TT];   // 25.6 KB
    const int tid = threadIdx.x;
    const int b  = blockIdx.x;
    const int tz = blockIdx.y;
    const int warp = tid >> 5;
    const int lane = tid & 31;

    // load scores block for this b
    const float4* src = (const float4*)(g_scores + b * LL * TT);
#pragma unroll
    for (int idx = tid; idx < LL * TT / 4; idx += 256)
        ((float4*)at)[idx] = src[idx];
    __syncthreads();

    // softmax per row (warp per l)
    for (int l = warp; l < LL; l += 8) {
        float v[8];
        float m = -1e30f;
#pragma unroll
        for (int i = 0; i < 8; i++) {
            v[i] = at[l * TT + lane + 32 * i];
            m = fmaxf(m, v[i]);
        }
#pragma unroll
        for (int s = 16; s; s >>= 1) m = fmaxf(m, __shfl_xor_sync(0xffffffffu, m, s));
        float ssum = 0.f;
#pragma unroll
        for (int i = 0; i < 8; i++) {
            v[i] = __expf(v[i] - m);
            ssum += v[i];
        }
#pragma unroll
        for (int s = 16; s; s >>= 1) ssum += __shfl_xor_sync(0xffffffffu, ssum, s);
        float inv = __fdividef(1.f, ssum);
#pragma unroll
        for (int i = 0; i < 8; i++) at[l * TT + lane + 32 * i] = v[i] * inv;
    }
    __syncthreads();

    // weighted sum over the 32-t chunk; thread owns half2 column c2 = tid
    const __half2* wfb = (const __half2*)g_wfh + (size_t)(b * TT + tz * TCH) * CC2 + tid;
    float2 acc[LL];
#pragma unroll
    for (int l = 0; l < LL; l++) acc[l] = make_float2(0.f, 0.f);

    for (int t4 = 0; t4 < TCH; t4 += 4) {
        float2 w0 = __half22float2(wfb[(t4 + 0) * CC2]);
        float2 w1 = __half22float2(wfb[(t4 + 1) * CC2]);
        float2 w2 = __half22float2(wfb[(t4 + 2) * CC2]);
        float2 w3 = __half22float2(wfb[(t4 + 3) * CC2]);
#pragma unroll
        for (int l = 0; l < LL; l++) {
            float4 a = *(const float4*)&at[l * TT + tz * TCH + t4];
            float sx = fmaf(a.x, w0.x, acc[l].x);
            float sy = fmaf(a.x, w0.y, acc[l].y);
            sx = fmaf(a.y, w1.x, sx);
            sy = fmaf(a.y, w1.y, sy);
            sx = fmaf(a.z, w2.x, sx);
            sy = fmaf(a.z, w2.y, sy);
            acc[l].x = fmaf(a.w, w3.x, sx);
            acc[l].y = fmaf(a.w, w3.y, sy);
        }
    }

    float* o = g_part + (size_t)((tz * BB + b) * LL) * CC + 2 * tid;
#pragma unroll
    for (int l = 0; l < LL; l++) *(float2*)&o[l * CC] = acc[l];
}

// ---------------------------------------------------------------------------
// Kernel B2b: reduce TSPLIT partials -> out.
// ---------------------------------------------------------------------------
__global__ __launch_bounds__(256) void pvam_reduce_kernel(float* __restrict__ out)
{
    const int i = blockIdx.x * 256 + threadIdx.x;      // float4 index
    const int STRIDE4 = BB * LL * CC / 4;              // 102400
    const float4* p = (const float4*)g_part;
    float4 r = p[i];
#pragma unroll
    for (int j = 1; j < TSPLIT; j++) {
        float4 v = p[i + j * STRIDE4];
        r.x += v.x; r.y += v.y; r.z += v.z; r.w += v.w;
    }
    ((float4*)out)[i] = r;
}

// ---------------------------------------------------------------------------
extern "C" void kernel_launch(void* const* d_in, const int* in_sizes, int n_in,
                              void* d_out, int out_size)
{
    const float* word_features = (const float*)d_in[0];  // (32,256,512)
    const float* word_fc_w     = (const float*)d_in[1];  // (512,512)
    const float* word_fc_b     = (const float*)d_in[2];  // (512,)
    const float* pos_emb       = (const float*)d_in[3];  // (25,512)
    const float* atten_w       = (const float*)d_in[4];  // (512,)
    const float* atten_b       = (const float*)d_in[5];  // (1,)
    float* out = (float*)d_out;                          // (32,25,512)

    wf_gemm_fp16<<<dim3(CC / 128, (BB * TT) / 128), 256>>>(
        word_features, word_fc_w, word_fc_b);
    scores_kernel<<<dim3(TT / 32, BB), 256>>>(pos_emb, atten_w, atten_b);
    pvam_part_kernel<<<dim3(BB, TSPLIT), 256>>>();
    pvam_reduce_kernel<<<(BB * LL * CC / 4) / 256, 256>>>(out);
}

// round 14
// speedup vs baseline: 1.7667x; 1.0262x over previous
#include <cuda_runtime.h>
#include <cuda_fp16.h>
#include <cuda_bf16.h>
#include <cstdint>

// Problem constants (fixed by reference)
#define BB 32
#define TT 256
#define CC 512
#define LL 25
#define CC2 (CC / 2)        // 256 half2 per row
#define CSPLIT 8            // c-slices for pvam (32 half2 each)

// Scratch in device globals (no allocations allowed in kernel_launch)
__device__ __half g_wfh[BB * TT * CC];               // 8 MB: post-FC features (fp16)
__device__ float  g_scores[BB * LL * TT];            // 0.8 MB: logits

// ---------------------------------------------------------------------------
__device__ __forceinline__ __half2 htanh2(__half2 x) {
    uint32_t xu = *(uint32_t*)&x, yu;
    asm("tanh.approx.f16x2 %0, %1;" : "=r"(yu) : "r"(xu));
    return *(__half2*)&yu;
}
__device__ __forceinline__ __half2 packh2(float lo, float hi) {
    return __float22half2_rn(make_float2(lo, hi));
}

// ---------------------------------------------------------------------------
// Kernel A: wf[m,n] = sum_k X[m,k]*W[n,k] + bias[n], stored as fp16.
// fp16 mma m16n8k16, fp32 accum. Block 128x128, BK=16, double-buffered.
// (unchanged — control)
// ---------------------------------------------------------------------------
#define PADH 24
__global__ __launch_bounds__(256, 2) void wf_gemm_fp16(
    const float* __restrict__ X,     // [8192, 512]
    const float* __restrict__ W,     // [512, 512] (row n, col k)
    const float* __restrict__ bias)  // [512]
{
    __shared__ __half As[2][128][PADH];
    __shared__ __half Bs[2][128][PADH];

    const int tid  = threadIdx.x;
    const int lane = tid & 31;
    const int warp = tid >> 5;
    const int g    = lane >> 2;
    const int tg   = lane & 3;
    const int wm   = (warp >> 2) << 6;
    const int wn   = (warp & 3) << 5;

    const int m0 = blockIdx.y << 7;
    const int n0 = blockIdx.x << 7;

    const int lr = tid >> 2;
    const int lc = (tid & 3) << 2;

    const float* Ag = X + (m0 + lr) * CC + lc;
    const float* Bg = W + (n0 + lr) * CC + lc;

    float acc[4][4][4];
#pragma unroll
    for (int mt = 0; mt < 4; mt++)
#pragma unroll
        for (int nt = 0; nt < 4; nt++)
#pragma unroll
            for (int i = 0; i < 4; i++) acc[mt][nt][i] = 0.f;

    float4 pa0, pa1, pb0, pb1;

#define CVT_STORE(dst, v)                                                     \
    do {                                                                      \
        __half2 h0 = __float22half2_rn(make_float2((v).x, (v).y));            \
        __half2 h1 = __float22half2_rn(make_float2((v).z, (v).w));            \
        *(uint2*)(dst) = make_uint2(*(uint32_t*)&h0, *(uint32_t*)&h1);        \
    } while (0)

#define GEMM_STORE_TILE(SS)                                                   \
    do {                                                                      \
        CVT_STORE(&As[SS][lr][lc], pa0);                                      \
        CVT_STORE(&As[SS][lr + 64][lc], pa1);                                 \
        CVT_STORE(&Bs[SS][lr][lc], pb0);                                      \
        CVT_STORE(&Bs[SS][lr + 64][lc], pb1);                                 \
    } while (0)

    pa0 = *(const float4*)(Ag);
    pa1 = *(const float4*)(Ag + 64 * CC);
    pb0 = *(const float4*)(Bg);
    pb1 = *(const float4*)(Bg + 64 * CC);
    GEMM_STORE_TILE(0);
    __syncthreads();

    int s = 0;
    for (int it = 0; it < 32; ++it) {
        if (it < 31) {
            const int ko = (it + 1) << 4;
            pa0 = *(const float4*)(Ag + ko);
            pa1 = *(const float4*)(Ag + 64 * CC + ko);
            pb0 = *(const float4*)(Bg + ko);
            pb1 = *(const float4*)(Bg + 64 * CC + ko);
        }
        {
            uint32_t af[4][4], bf[4][2];
#pragma unroll
            for (int mt = 0; mt < 4; mt++) {
                const int r = wm + (mt << 4) + g;
                af[mt][0] = *(const uint32_t*)&As[s][r][2 * tg];
                af[mt][1] = *(const uint32_t*)&As[s][r + 8][2 * tg];
                af[mt][2] = *(const uint32_t*)&As[s][r][2 * tg + 8];
                af[mt][3] = *(const uint32_t*)&As[s][r + 8][2 * tg + 8];
            }
#pragma unroll
            for (int nt = 0; nt < 4; nt++) {
                const int r = wn + (nt << 3) + g;
                bf[nt][0] = *(const uint32_t*)&Bs[s][r][2 * tg];
                bf[nt][1] = *(const uint32_t*)&Bs[s][r][2 * tg + 8];
            }
#pragma unroll
            for (int mt = 0; mt < 4; mt++)
#pragma unroll
                for (int nt = 0; nt < 4; nt++) {
                    asm volatile(
                        "mma.sync.aligned.m16n8k16.row.col.f32.f16.f16.f32 "
                        "{%0,%1,%2,%3}, {%4,%5,%6,%7}, {%8,%9}, {%0,%1,%2,%3};"
                        : "+f"(acc[mt][nt][0]), "+f"(acc[mt][nt][1]),
                          "+f"(acc[mt][nt][2]), "+f"(acc[mt][nt][3])
                        : "r"(af[mt][0]), "r"(af[mt][1]),
                          "r"(af[mt][2]), "r"(af[mt][3]),
                          "r"(bf[nt][0]), "r"(bf[nt][1]));
                }
        }
        if (it < 31) {
            const int ns = s ^ 1;
            GEMM_STORE_TILE(ns);
            __syncthreads();
            s = ns;
        }
    }

    // Epilogue: add bias, convert to fp16, store.
#pragma unroll
    for (int nt = 0; nt < 4; nt++) {
        const int n = n0 + wn + (nt << 3) + (tg << 1);
        const float b0v = bias[n];
        const float b1v = bias[n + 1];
#pragma unroll
        for (int mt = 0; mt < 4; mt++) {
            const int m = m0 + wm + (mt << 4) + g;
            __half2 h0 = packh2(acc[mt][nt][0] + b0v, acc[mt][nt][1] + b1v);
            __half2 h1 = packh2(acc[mt][nt][2] + b0v, acc[mt][nt][3] + b1v);
            *(__half2*)&g_wfh[m * CC + n]       = h0;
            *(__half2*)&g_wfh[(m + 8) * CC + n] = h1;
        }
    }
#undef GEMM_STORE_TILE
#undef CVT_STORE
}

// ---------------------------------------------------------------------------
// Kernel B1: scores[b,l,t] (unchanged — control)
// ---------------------------------------------------------------------------
__global__ __launch_bounds__(256) void scores_kernel(
    const float* __restrict__ pos_emb,   // [25, 512]
    const float* __restrict__ atten_w,   // [512]
    const float* __restrict__ atten_b)   // [1]
{
    const int warp = threadIdx.x >> 5;
    const int lane = threadIdx.x & 31;
    const int b = blockIdx.y;
    const int t0 = blockIdx.x * 32 + warp * 4;

    const float4* awr = (const float4*)atten_w;

    __half2 wfh[4][8];
    float4 aw4[4];
#pragma unroll
    for (int r = 0; r < 4; r++) {
        const uint2* wfr = (const uint2*)(g_wfh + (b * TT + t0 + r) * CC);
#pragma unroll
        for (int i = 0; i < 4; i++) {
            uint2 u = wfr[lane + 32 * i];
            wfh[r][2 * i]     = *(__half2*)&u.x;
            wfh[r][2 * i + 1] = *(__half2*)&u.y;
        }
    }
#pragma unroll
    for (int i = 0; i < 4; i++) aw4[i] = awr[lane + 32 * i];
    const float bsc = atten_b[0];

#pragma unroll 2
    for (int l = 0; l < LL; l++) {
        const float4* pr = (const float4*)(pos_emb + l * CC);
        float acc0 = 0.f, acc1 = 0.f, acc2 = 0.f, acc3 = 0.f;
#pragma unroll
        for (int i = 0; i < 4; i++) {
            float4 p = __ldg(&pr[lane + 32 * i]);
            __half2 p01 = packh2(p.x, p.y);
            __half2 p23 = packh2(p.z, p.w);

            __half2 tA0 = htanh2(__hadd2(wfh[0][2 * i], p01));
            __half2 tA1 = htanh2(__hadd2(wfh[0][2 * i + 1], p23));
            __half2 tB0 = htanh2(__hadd2(wfh[1][2 * i], p01));
            __half2 tB1 = htanh2(__hadd2(wfh[1][2 * i + 1], p23));
            __half2 tC0 = htanh2(__hadd2(wfh[2][2 * i], p01));
            __half2 tC1 = htanh2(__hadd2(wfh[2][2 * i + 1], p23));
            __half2 tD0 = htanh2(__hadd2(wfh[3][2 * i], p01));
            __half2 tD1 = htanh2(__hadd2(wfh[3][2 * i + 1], p23));

            acc0 = fmaf(__low2float(tA0),  aw4[i].x, acc0);
            acc0 = fmaf(__high2float(tA0), aw4[i].y, acc0);
            acc0 = fmaf(__low2float(tA1),  aw4[i].z, acc0);
            acc0 = fmaf(__high2float(tA1), aw4[i].w, acc0);
            acc1 = fmaf(__low2float(tB0),  aw4[i].x, acc1);
            acc1 = fmaf(__high2float(tB0), aw4[i].y, acc1);
            acc1 = fmaf(__low2float(tB1),  aw4[i].z, acc1);
            acc1 = fmaf(__high2float(tB1), aw4[i].w, acc1);
            acc2 = fmaf(__low2float(tC0),  aw4[i].x, acc2);
            acc2 = fmaf(__high2float(tC0), aw4[i].y, acc2);
            acc2 = fmaf(__low2float(tC1),  aw4[i].z, acc2);
            acc2 = fmaf(__high2float(tC1), aw4[i].w, acc2);
            acc3 = fmaf(__low2float(tD0),  aw4[i].x, acc3);
            acc3 = fmaf(__high2float(tD0), aw4[i].y, acc3);
            acc3 = fmaf(__low2float(tD1),  aw4[i].z, acc3);
            acc3 = fmaf(__high2float(tD1), aw4[i].w, acc3);
        }
#pragma unroll
        for (int s = 16; s; s >>= 1) {
            acc0 += __shfl_xor_sync(0xffffffffu, acc0, s);
            acc1 += __shfl_xor_sync(0xffffffffu, acc1, s);
            acc2 += __shfl_xor_sync(0xffffffffu, acc2, s);
            acc3 += __shfl_xor_sync(0xffffffffu, acc3, s);
        }
        if (lane == 0) {
            *(float4*)&g_scores[(b * LL + l) * TT + t0] =
                make_float4(acc0 + bsc, acc1 + bsc, acc2 + bsc, acc3 + bsc);
        }
    }
}

// ---------------------------------------------------------------------------
// Kernel B2 (new): softmax + pvam in ONE kernel, c-split, no partial buffer.
// grid = (CSPLIT, B) = 256 CTAs, 256 threads.
// Each CTA: softmax the b's 25x256 score block in smem (redundant x8, cheap),
// then warp w accumulates t-chunk [32w, 32w+32) for 32 half2 columns
// (lane = column), fp32 accum; cross-warp combine via smem; write out.
// ---------------------------------------------------------------------------
__global__ __launch_bounds__(256) void pvam_kernel(float* __restrict__ out)
{
    extern __shared__ float sm[];
    float*  at  = sm;                          // [LL*TT] 25.6 KB
    float2* red = (float2*)(sm + LL * TT);     // [8][LL][32] 51.2 KB

    const int tid  = threadIdx.x;
    const int cz   = blockIdx.x;
    const int b    = blockIdx.y;
    const int warp = tid >> 5;
    const int lane = tid & 31;

    // load scores block for this b
    const float4* src = (const float4*)(g_scores + b * LL * TT);
    for (int idx = tid; idx < LL * TT / 4; idx += 256)
        ((float4*)at)[idx] = src[idx];
    __syncthreads();

    // softmax per row (warp per l)
    for (int l = warp; l < LL; l += 8) {
        float v[8];
        float m = -1e30f;
#pragma unroll
        for (int i = 0; i < 8; i++) {
            v[i] = at[l * TT + lane + 32 * i];
            m = fmaxf(m, v[i]);
        }
#pragma unroll
        for (int s = 16; s; s >>= 1) m = fmaxf(m, __shfl_xor_sync(0xffffffffu, m, s));
        float ssum = 0.f;
#pragma unroll
        for (int i = 0; i < 8; i++) {
            v[i] = __expf(v[i] - m);
            ssum += v[i];
        }
#pragma unroll
        for (int s = 16; s; s >>= 1) ssum += __shfl_xor_sync(0xffffffffu, ssum, s);
        float inv = __fdividef(1.f, ssum);
#pragma unroll
        for (int i = 0; i < 8; i++) at[l * TT + lane + 32 * i] = v[i] * inv;
    }
    __syncthreads();

    // accumulate: warp w handles t in [32w, 32w+32); lane owns half2 column
    const int c2 = cz * 32 + lane;
    const int tbase = warp * 32;
    const __half2* wfb = (const __half2*)g_wfh
                       + (size_t)(b * TT + tbase) * CC2 + c2;

    float2 acc[LL];
#pragma unroll
    for (int l = 0; l < LL; l++) acc[l] = make_float2(0.f, 0.f);

    for (int t4 = 0; t4 < 32; t4 += 4) {
        float2 w0 = __half22float2(wfb[(t4 + 0) * CC2]);
        float2 w1 = __half22float2(wfb[(t4 + 1) * CC2]);
        float2 w2 = __half22float2(wfb[(t4 + 2) * CC2]);
        float2 w3 = __half22float2(wfb[(t4 + 3) * CC2]);
#pragma unroll
        for (int l = 0; l < LL; l++) {
            float4 a = *(const float4*)&at[l * TT + tbase + t4];  // broadcast
            float sx = fmaf(a.x, w0.x, acc[l].x);
            float sy = fmaf(a.x, w0.y, acc[l].y);
            sx = fmaf(a.y, w1.x, sx);
            sy = fmaf(a.y, w1.y, sy);
            sx = fmaf(a.z, w2.x, sx);
            sy = fmaf(a.z, w2.y, sy);
            acc[l].x = fmaf(a.w, w3.x, sx);
            acc[l].y = fmaf(a.w, w3.y, sy);
        }
    }

    // stash warp partials
#pragma unroll
    for (int l = 0; l < LL; l++)
        red[(warp * LL + l) * 32 + lane] = acc[l];
    __syncthreads();

    // combine 8 warp partials and write directly to out
    for (int idx = tid; idx < LL * 32; idx += 256) {
        const int l = idx >> 5;
        const int c = idx & 31;
        float2 s = red[(0 * LL + l) * 32 + c];
#pragma unroll
        for (int w = 1; w < 8; w++) {
            float2 v = red[(w * LL + l) * 32 + c];
            s.x += v.x;
            s.y += v.y;
        }
        *(float2*)&out[(size_t)(b * LL + l) * CC + (cz * 32 + c) * 2] = s;
    }
}

// ---------------------------------------------------------------------------
extern "C" void kernel_launch(void* const* d_in, const int* in_sizes, int n_in,
                              void* d_out, int out_size)
{
    const float* word_features = (const float*)d_in[0];  // (32,256,512)
    const float* word_fc_w     = (const float*)d_in[1];  // (512,512)
    const float* word_fc_b     = (const float*)d_in[2];  // (512,)
    const float* pos_emb       = (const float*)d_in[3];  // (25,512)
    const float* atten_w       = (const float*)d_in[4];  // (512,)
    const float* atten_b       = (const float*)d_in[5];  // (1,)
    float* out = (float*)d_out;                          // (32,25,512)

    const int pvam_smem = (LL * TT) * 4 + 8 * LL * 32 * 8;  // 76800 B
    cudaFuncSetAttribute(pvam_kernel,
                         cudaFuncAttributeMaxDynamicSharedMemorySize, pvam_smem);

    wf_gemm_fp16<<<dim3(CC / 128, (BB * TT) / 128), 256>>>(
        word_features, word_fc_w, word_fc_b);
    scores_kernel<<<dim3(TT / 32, BB), 256>>>(pos_emb, atten_w, atten_b);
    pvam_kernel<<<dim3(CSPLIT, BB), 256, pvam_smem>>>(out);
}